// round 1
// baseline (speedup 1.0000x reference)
#include <cuda_runtime.h>
#include <math_constants.h>

// Per-row partial results. B = 4096 in this problem; pad for safety.
#define MAX_B 8192
__device__ float g_partials[MAX_B];

#define DEPTH_PARAM 0.5f
#define LENGTH_PENALTY 1.5f

struct ArgMax { float v; int i; };

__device__ __forceinline__ void am_update(ArgMax& a, float v, int i) {
    // strict > keeps first occurrence (lowest index) on ties within a thread,
    // since indices are visited in increasing order per thread.
    if (v > a.v) { a.v = v; a.i = i; }
}

__device__ __forceinline__ void am_combine(ArgMax& a, float v, int i) {
    if (v > a.v || (v == a.v && i < a.i)) { a.v = v; a.i = i; }
}

__device__ __forceinline__ ArgMax warp_reduce(ArgMax a) {
    #pragma unroll
    for (int off = 16; off; off >>= 1) {
        float ov = __shfl_down_sync(0xffffffffu, a.v, off);
        int   oi = __shfl_down_sync(0xffffffffu, a.i, off);
        am_combine(a, ov, oi);
    }
    return a;
}

// One block per batch row. Dual argmax (y_pred, y_true) + tree-walk epilogue.
__global__ __launch_bounds__(256, 8)
void hloss_row_kernel(const float* __restrict__ y_pred,
                      const float* __restrict__ y_true,
                      const float* __restrict__ class_weights,
                      const int*   __restrict__ path_ids,
                      const int*   __restrict__ path_len,
                      const int*   __restrict__ sib_start,
                      const int*   __restrict__ sib_size,
                      int C, int D)
{
    const int b   = blockIdx.x;
    const int tid = threadIdx.x;
    const int nth = blockDim.x;

    const float* __restrict__ rp = y_pred + (size_t)b * C;
    const float* __restrict__ rt = y_true + (size_t)b * C;

    ArgMax ap; ap.v = -CUDART_INF_F; ap.i = 0;
    ArgMax at; at.v = -CUDART_INF_F; at.i = 0;

    // Vectorized main loop. C = 2728 is divisible by 4 and rows are 16B-aligned
    // (C*4 = 10912 bytes, multiple of 16); keep a scalar tail for robustness.
    const int C4 = C >> 2;
    const float4* __restrict__ rp4 = (const float4*)rp;
    const float4* __restrict__ rt4 = (const float4*)rt;

    for (int i = tid; i < C4; i += nth) {
        const int base = i << 2;
        float4 vp = rp4[i];
        float4 vt = rt4[i];
        am_update(ap, vp.x, base + 0);
        am_update(ap, vp.y, base + 1);
        am_update(ap, vp.z, base + 2);
        am_update(ap, vp.w, base + 3);
        am_update(at, vt.x, base + 0);
        am_update(at, vt.y, base + 1);
        am_update(at, vt.z, base + 2);
        am_update(at, vt.w, base + 3);
    }
    for (int i = (C4 << 2) + tid; i < C; i += nth) {
        am_update(ap, rp[i], i);
        am_update(at, rt[i], i);
    }

    // Block reduction of the two (val, idx) pairs.
    __shared__ float s_pv[8]; __shared__ int s_pi[8];
    __shared__ float s_tv[8]; __shared__ int s_ti[8];

    ap = warp_reduce(ap);
    at = warp_reduce(at);
    const int lane = tid & 31;
    const int wid  = tid >> 5;
    if (lane == 0) { s_pv[wid] = ap.v; s_pi[wid] = ap.i;
                     s_tv[wid] = at.v; s_ti[wid] = at.i; }
    __syncthreads();

    if (tid == 0) {
        const int nwarps = nth >> 5;
        ArgMax fp; fp.v = s_pv[0]; fp.i = s_pi[0];
        ArgMax ft; ft.v = s_tv[0]; ft.i = s_ti[0];
        for (int w = 1; w < nwarps; w++) {
            am_combine(fp, s_pv[w], s_pi[w]);
            am_combine(ft, s_tv[w], s_ti[w]);
        }
        const int pt = fp.i;              // pred_top
        const int tt = ft.i;              // true_top

        const int lp = path_len[pt];
        const int lt = path_len[tt];
        const int diff = abs(lp - lt);

        float total = 0.0f;
        if (diff != 0) {
            const int lmin = (lp < lt) ? lp : lt;
            float local = 0.0f;
            for (int l = 0; l < lmin; l++) {
                const int st = sib_start[tt * D + l];
                const int sz = sib_size [tt * D + l];
                // lse over (y_pred * 0/1-mask): masked-out classes contribute exp(0)=1.
                float s = (float)(C - sz);
                for (int j = 0; j < sz; j++) s += expf(rp[st + j]);
                const float lse = logf(s);
                const float tl  = rp[path_ids[tt * D + l]];
                const float h   = (float)(lt - l - 1);
                local += expf(-DEPTH_PARAM * h) * (lse - tl);
            }
            total = local * (LENGTH_PENALTY * (float)diff) * class_weights[tt];
        }
        g_partials[b] = total;
    }
}

// Deterministic final sum (fixed order), divided by B.
__global__ void hloss_reduce_kernel(float* __restrict__ out, int B)
{
    __shared__ float sm[1024];
    float s = 0.0f;
    for (int i = threadIdx.x; i < B; i += 1024) s += g_partials[i];
    sm[threadIdx.x] = s;
    __syncthreads();
    #pragma unroll
    for (int k = 512; k > 0; k >>= 1) {
        if (threadIdx.x < k) sm[threadIdx.x] += sm[threadIdx.x + k];
        __syncthreads();
    }
    if (threadIdx.x == 0) out[0] = sm[0] / (float)B;
}

extern "C" void kernel_launch(void* const* d_in, const int* in_sizes, int n_in,
                              void* d_out, int out_size)
{
    const float* y_pred        = (const float*)d_in[0];
    const float* y_true        = (const float*)d_in[1];
    const float* class_weights = (const float*)d_in[2];
    const int*   path_ids      = (const int*)  d_in[3];
    const int*   path_len      = (const int*)  d_in[4];
    const int*   sib_start     = (const int*)  d_in[5];
    const int*   sib_size      = (const int*)  d_in[6];

    const int C = in_sizes[2];              // class_weights has C elements
    const int B = in_sizes[0] / C;          // y_pred is [B, C]
    const int D = in_sizes[3] / C;          // path_ids is [C, D]

    hloss_row_kernel<<<B, 256>>>(y_pred, y_true, class_weights,
                                 path_ids, path_len, sib_start, sib_size, C, D);
    hloss_reduce_kernel<<<1, 1024>>>((float*)d_out, B);
}